// round 8
// baseline (speedup 1.0000x reference)
#include <cuda_runtime.h>
#include <cuda_fp16.h>
#include <cstdint>

#define BB 8
#define CC 64
#define NN 4096
#define KK 20
#define NCAND 48
#define NTARGET 24
#define OUTC 64
#define TM 128
#define TN 128

// ===================== device scratch (allocation-free) =====================
__device__ __half g_hi[(size_t)BB * NN * CC];
__device__ float g_xp[(size_t)BB * NN * CC];          // point-major fp32 copy
__device__ float g_sq[BB * NN];
__device__ unsigned short g_scor[(size_t)BB * NN * NN];  // flipped-fp16 scores, 256MB
__device__ int   g_idx[BB * NN * KK];
__device__ float g_u[(size_t)BB * NN * OUTC];
__device__ float g_v[(size_t)BB * NN * OUTC];
__device__ float g_mx[(size_t)BB * NN * OUTC];
__device__ float g_mn[(size_t)BB * NN * OUTC];
__device__ float g_sum[OUTC];
__device__ float g_sumsq[OUTC];
__device__ float g_s[OUTC];
__device__ float g_t[OUTC];

// ===================== helpers =====================
__device__ __forceinline__ void ldsm_x4(uint32_t addr, uint32_t* r) {
    asm volatile("ldmatrix.sync.aligned.m8n8.x4.shared.b16 {%0,%1,%2,%3}, [%4];"
                 : "=r"(r[0]), "=r"(r[1]), "=r"(r[2]), "=r"(r[3]) : "r"(addr));
}
__device__ __forceinline__ void mma16816(float* d, const uint32_t* a, const uint32_t* b) {
    asm volatile("mma.sync.aligned.m16n8k16.row.col.f32.f16.f16.f32 "
                 "{%0,%1,%2,%3}, {%4,%5,%6,%7}, {%8,%9}, {%0,%1,%2,%3};"
                 : "+f"(d[0]), "+f"(d[1]), "+f"(d[2]), "+f"(d[3])
                 : "r"(a[0]), "r"(a[1]), "r"(a[2]), "r"(a[3]), "r"(b[0]), "r"(b[1]));
}
__device__ __forceinline__ uint32_t smem_u32(const void* p) {
    uint32_t a;
    asm("{ .reg .u64 t; cvta.to.shared.u64 t, %1; cvt.u32.u64 %0, t; }" : "=r"(a) : "l"(p));
    return a;
}
// two floats -> two flipped-fp16 (monotone: smaller float => smaller u16), packed
__device__ __forceinline__ uint32_t fflip16x2(float a, float b) {
    __half2 h2 = __floats2half2_rn(a, b);
    uint32_t u = *reinterpret_cast<uint32_t*>(&h2);
    uint32_t xorv = 0x80008000u | (((u >> 15) & 0x00010001u) * 0x7FFFu);
    return u ^ xorv;
}

// ===================== kernel A: sq norms + fp16 hi + fp32 point-major =====================
__global__ void __launch_bounds__(128) prep_kernel(const float* __restrict__ x) {
    int p = blockIdx.x * 128 + threadIdx.x;
    int b = p >> 12;
    int n = p & (NN - 1);
    const float* xb = x + (size_t)b * CC * NN + n;
    float s = 0.f;
#pragma unroll
    for (int g = 0; g < 8; g++) {
        uint4 h4;
        unsigned short* hp = (unsigned short*)&h4;
        float vf[8];
#pragma unroll
        for (int e = 0; e < 8; e++) {
            float v = xb[(size_t)(g * 8 + e) * NN];
            vf[e] = v;
            s = fmaf(v, v, s);
            hp[e] = __half_as_ushort(__float2half_rn(v));
        }
        *reinterpret_cast<uint4*>(g_hi + (size_t)p * CC + g * 8) = h4;
        *reinterpret_cast<float4*>(g_xp + (size_t)p * CC + g * 8) =
            make_float4(vf[0], vf[1], vf[2], vf[3]);
        *reinterpret_cast<float4*>(g_xp + (size_t)p * CC + g * 8 + 4) =
            make_float4(vf[4], vf[5], vf[6], vf[7]);
    }
    g_sq[p] = s;
    if (blockIdx.x == 0 && threadIdx.x < OUTC) {
        g_sum[threadIdx.x] = 0.f;
        g_sumsq[threadIdx.x] = 0.f;
    }
}

// ===================== kernel B1: triangular HMMA GEMM -> flipped-fp16 scores =====================
#define SM_A     0          /* 128*144 = 18432 */
#define SM_B     18432      /* 2*18432 = 36864 */
#define SM_SQS   55296      /* 2*128*4 = 1024 */
#define SM_DTT   56320      /* 128 rows * 136 u16 = 34816 (transpose staging) */
#define SM_TOTAL 91136

__global__ void __launch_bounds__(256, 2) knn_gemm_kernel() {
    extern __shared__ char sm[];
    const uint32_t smb = smem_u32(sm);
    const int tid = threadIdx.x;
    const int wid = tid >> 5;
    const int lane = tid & 31;

    // ---- balanced triangular schedule: bid and bid+148 land on the same SM ----
    int bid = blockIdx.x;
    int rt, b;
    if (bid < 108)      { rt = bid % 27;            b = bid / 27; }
    else if (bid < 148) { int s = bid - 108; rt = 27 + s % 5; b = s / 5; }
    else                { int j = bid - 148; rt = 26 - (j % 27); b = 4 + j / 27; }
    const int row0 = rt * TM;

    const __half* hi_b = g_hi + (size_t)b * NN * CC;
    float* sqs = (float*)(sm + SM_SQS);
    uint32_t* dt = (uint32_t*)(sm + SM_DTT);      // [c][r2] stride 68 u32

    // load A rows, padded stride 144B
    for (int t = 0; t < 4; t++) {
        int i = tid + t * 256;
        int m = i >> 3, j = i & 7;
        *reinterpret_cast<uint4*>(sm + SM_A + m * 144 + j * 16) =
            *reinterpret_cast<const uint4*>(hi_b + (size_t)(row0 + m) * CC + j * 8);
    }
    // B tile 0
    for (int t = 0; t < 4; t++) {
        int i = tid + t * 256;
        int n = i >> 3, j = i & 7;
        *reinterpret_cast<uint4*>(sm + SM_B + n * 144 + j * 16) =
            *reinterpret_cast<const uint4*>(hi_b + (size_t)n * CC + j * 8);
    }
    if (tid < 128) sqs[tid] = g_sq[b * NN + tid];
    __syncthreads();

    const int m0 = wid * 16;
    const int g = lane >> 2, t4 = lane & 3;
    // own-row squared norms for the transpose path
    const float sqr0 = g_sq[b * NN + row0 + m0 + g];
    const float sqr1 = g_sq[b * NN + row0 + m0 + g + 8];
    uint4 pre[4];
    float sqnext = 0.f;

    for (int ct = 0; ct <= rt; ct++) {
        int buf = ct & 1;
        uint32_t bsm = smb + SM_B + (uint32_t)buf * 18432u;

        // prefetch next B tile + sq to registers (overlaps MMA)
        if (ct < rt) {
            int col0 = (ct + 1) * TN;
#pragma unroll
            for (int t = 0; t < 4; t++) {
                int i = tid + t * 256;
                int n = i >> 3, j = i & 7;
                pre[t] = *reinterpret_cast<const uint4*>(hi_b + (size_t)(col0 + n) * CC + j * 8);
            }
            if (tid < 128) sqnext = g_sq[b * NN + col0 + tid];
        }

        // ---- MMA: D[128x128] = A(128x64) . B^T(64x128) ----
        float acc[16][4];
#pragma unroll
        for (int nt = 0; nt < 16; nt++)
#pragma unroll
            for (int e = 0; e < 4; e++) acc[nt][e] = 0.f;

#pragma unroll
        for (int ks = 0; ks < 4; ks++) {
            uint32_t ah[4];
            uint32_t aoff = (uint32_t)(m0 + (lane & 15)) * 144u +
                            (uint32_t)(ks * 16 + ((lane >> 4) << 3)) * 2u;
            ldsm_x4(smb + SM_A + aoff, ah);
#pragma unroll
            for (int ntp = 0; ntp < 8; ntp++) {
                uint32_t bh[4];
                uint32_t bn = (uint32_t)(ntp * 16 + ((lane >> 4) << 3) + (lane & 7));
                uint32_t bk = (uint32_t)(ks * 16 + (((lane >> 3) & 1) << 3));
                ldsm_x4(bsm + bn * 144u + bk * 2u, bh);
                mma16816(acc[2 * ntp],     ah, bh);
                mma16816(acc[2 * ntp + 1], ah, bh + 2);
            }
        }

        __syncthreads();   // MMA reads of B[buf] done; prev copy-out of dt done

        // store next B tile + sqs
        if (ct < rt) {
            char* dstb = sm + SM_B + (buf ^ 1) * 18432;
#pragma unroll
            for (int t = 0; t < 4; t++) {
                int i = tid + t * 256;
                int n = i >> 3, j = i & 7;
                *reinterpret_cast<uint4*>(dstb + n * 144 + j * 16) = pre[t];
            }
            if (tid < 128) sqs[(buf ^ 1) * 128 + tid] = sqnext;
        }

        // ---- epilogue: normal block (rt,ct) stores + transpose staging ----
        {
            const float* sqb = sqs + buf * 128;
            unsigned short* dout = g_scor + ((size_t)(b * NN) + row0 + m0 + g) * NN + ct * TN;
            const bool do_t = (ct < rt);
            const int r2 = (m0 + g) >> 1;
#pragma unroll
            for (int nt = 0; nt < 16; nt++) {
                int c0 = nt * 8 + t4 * 2;
                float2 sq2 = *reinterpret_cast<const float2*>(sqb + c0);
                uint32_t o0 = fflip16x2(fmaf(-2.f, acc[nt][0], sq2.x),
                                        fmaf(-2.f, acc[nt][1], sq2.y));
                uint32_t o1 = fflip16x2(fmaf(-2.f, acc[nt][2], sq2.x),
                                        fmaf(-2.f, acc[nt][3], sq2.y));
                *reinterpret_cast<uint32_t*>(dout + c0) = o0;
                *reinterpret_cast<uint32_t*>(dout + (size_t)8 * NN + c0) = o1;

                if (do_t) {
                    uint32_t pT01 = fflip16x2(fmaf(-2.f, acc[nt][0], sqr0),
                                              fmaf(-2.f, acc[nt][1], sqr0));
                    uint32_t pT23 = fflip16x2(fmaf(-2.f, acc[nt][2], sqr1),
                                              fmaf(-2.f, acc[nt][3], sqr1));
                    uint32_t q01 = __shfl_down_sync(0xffffffffu, pT01, 4);
                    uint32_t q23 = __shfl_down_sync(0xffffffffu, pT23, 4);
                    if (!(g & 1)) {
                        dt[(c0)     * 68 + r2]     = __byte_perm(pT01, q01, 0x5410);
                        dt[(c0 + 1) * 68 + r2]     = __byte_perm(pT01, q01, 0x7632);
                        dt[(c0)     * 68 + r2 + 4] = __byte_perm(pT23, q23, 0x5410);
                        dt[(c0 + 1) * 68 + r2 + 4] = __byte_perm(pT23, q23, 0x7632);
                    }
                }
            }
        }
        __syncthreads();   // B[buf^1] + dt staging complete

        // ---- copy-out transposed block (ct, rt), coalesced ----
        if (ct < rt) {
            int col0 = ct * TN;
#pragma unroll
            for (int t = 0; t < 32; t++) {
                int i = tid + t * 256;
                int c = i >> 6, k = i & 63;
                uint32_t val = dt[c * 68 + k];
                size_t off32 = (size_t)(b * NN + col0 + c) * (NN / 2) + (row0 >> 1) + k;
                reinterpret_cast<uint32_t*>(g_scor)[off32] = val;
            }
        }
    }
}

// ===================== kernel B2: fused select (binary search) + exact rerank =====================
__global__ void __launch_bounds__(128) select_rerank_kernel() {
    __shared__ uint32_t wsum[2][4];
    __shared__ uint32_t counter;
    __shared__ int   cidx[NCAND];
    __shared__ float csc[NCAND];

    const int tid = threadIdx.x;
    const int wrp = tid >> 5;
    const int lane = tid & 31;
    const int p = blockIdx.x;
    const uint4* r4 = reinterpret_cast<const uint4*>(g_scor + (size_t)p * NN);

    // load 32 u16 scores per thread (coalesced uint4)
    uint4 v[4];
#pragma unroll
    for (int j = 0; j < 4; j++) v[j] = r4[j * 128 + tid];

    uint32_t lo = 0, hi = 0x10000u, cut = 0x10000u;

#pragma unroll 1
    for (int it = 0; it < 17; it++) {
        uint32_t mid = (lo + hi) >> 1;
        uint32_t c = 0;
#pragma unroll
        for (int j = 0; j < 4; j++) {
            const uint32_t* u4 = (const uint32_t*)&v[j];
#pragma unroll
            for (int e = 0; e < 4; e++) {
                uint32_t u = u4[e];
                c += ((u & 0xFFFFu) < mid) + ((u >> 16) < mid);
            }
        }
        c = __reduce_add_sync(0xffffffffu, c);
        if (lane == 0) wsum[it & 1][wrp] = c;
        __syncthreads();
        uint32_t tot = wsum[it & 1][0] + wsum[it & 1][1] + wsum[it & 1][2] + wsum[it & 1][3];
        if (tot >= NTARGET && tot <= NCAND) { cut = mid; break; }
        if (tot >= NTARGET) hi = mid; else lo = mid;
        if (hi - lo <= 1) { cut = hi; break; }
    }

    if (tid == 0) counter = 0;
    __syncthreads();

    // compaction into smem
#pragma unroll
    for (int j = 0; j < 4; j++) {
        const uint32_t* u4 = (const uint32_t*)&v[j];
#pragma unroll
        for (int e = 0; e < 4; e++) {
            uint32_t u = u4[e];
            int i32 = 4 * (j * 128 + tid) + e;
            if ((u & 0xFFFFu) < cut) {
                uint32_t slot = atomicAdd(&counter, 1);
                if (slot < NCAND) cidx[slot] = 2 * i32;
            }
            if ((u >> 16) < cut) {
                uint32_t slot = atomicAdd(&counter, 1);
                if (slot < NCAND) cidx[slot] = 2 * i32 + 1;
            }
        }
    }
    __syncthreads();
    int cnt = counter < NCAND ? (int)counter : NCAND;
    int bbase = (p >> 12) << 12;

    // exact fp32 rescoring: one thread per candidate
    if (tid < NCAND) {
        if (tid < cnt) {
            int c = cidx[tid];
            const float* xr = g_xp + (size_t)p * CC;
            const float* xc = g_xp + (size_t)(bbase + c) * CC;
            float d = 0.f;
#pragma unroll
            for (int i = 0; i < 16; i++) {
                float4 a = *reinterpret_cast<const float4*>(xr + i * 4);
                float4 bq = *reinterpret_cast<const float4*>(xc + i * 4);
                d = fmaf(a.x, bq.x, d);
                d = fmaf(a.y, bq.y, d);
                d = fmaf(a.z, bq.z, d);
                d = fmaf(a.w, bq.w, d);
            }
            csc[tid] = fmaf(-2.f, d, g_sq[bbase + c]);
        } else {
            csc[tid] = 3.0e38f;
            cidx[tid] = 0x7fffffff;
        }
    }
    __syncthreads();

    // rank counting -> top-20
    if (tid < NCAND) {
        float s = csc[tid];
        int   ii = cidx[tid];
        int r = 0;
#pragma unroll
        for (int j = 0; j < NCAND; j++) {
            float sj = csc[j];
            int ij = cidx[j];
            r += (sj < s) || (sj == s && ij < ii);
        }
        if (r < KK) g_idx[(size_t)p * KK + r] = ii;
    }
}

// ===================== kernel C: u = W1 @ x, v = (W2-W1) @ x (8 outputs/thread) =====================
__global__ void __launch_bounds__(128) gemm_uv_kernel(const float* __restrict__ x,
                                                      const float* __restrict__ W) {
    int b = blockIdx.z, og = blockIdx.y;
    int n = blockIdx.x * 128 + threadIdx.x;

    __shared__ float W1s[8][64];
    __shared__ float Wds[8][64];
    for (int i = threadIdx.x; i < 8 * 64; i += 128) {
        int oo = i >> 6, c = i & 63;
        int o = og * 8 + oo;
        float w1 = W[o * 2 * CC + c];
        float w2 = W[o * 2 * CC + CC + c];
        W1s[oo][c] = w1;
        Wds[oo][c] = w2 - w1;
    }
    __syncthreads();

    float ua[8], va[8];
#pragma unroll
    for (int oo = 0; oo < 8; oo++) { ua[oo] = 0.f; va[oo] = 0.f; }

    const float* xb = x + (size_t)b * CC * NN + n;
#pragma unroll
    for (int ch = 0; ch < CC; ch++) {
        float xv = xb[(size_t)ch * NN];
#pragma unroll
        for (int oo = 0; oo < 8; oo++) {
            ua[oo] = fmaf(W1s[oo][ch], xv, ua[oo]);
            va[oo] = fmaf(Wds[oo][ch], xv, va[oo]);
        }
    }

    float* up = g_u + ((size_t)b * NN + n) * OUTC + og * 8;
    float* vp = g_v + ((size_t)b * NN + n) * OUTC + og * 8;
#pragma unroll
    for (int oo = 0; oo < 8; oo += 4) {
        *reinterpret_cast<float4*>(up + oo) = make_float4(ua[oo], ua[oo + 1], ua[oo + 2], ua[oo + 3]);
        *reinterpret_cast<float4*>(vp + oo) = make_float4(va[oo], va[oo + 1], va[oo + 2], va[oo + 3]);
    }
}

// ===================== kernel D: edges =====================
__global__ void __launch_bounds__(256) edge_kernel() {
    __shared__ float ssum[OUTC];
    __shared__ float ssq[OUTC];
    int tid = threadIdx.x, lane = tid & 31, wrp = tid >> 5;
    if (tid < OUTC) { ssum[tid] = 0.f; ssq[tid] = 0.f; }
    __syncthreads();

    int p0 = blockIdx.x * 64;
    float lsum0 = 0.f, lsq0 = 0.f, lsum1 = 0.f, lsq1 = 0.f;

    for (int i = 0; i < 8; i++) {
        int p = p0 + wrp * 8 + i;
        const float* vp = g_v + (size_t)p * OUTC;
        float v0 = vp[lane], v1 = vp[lane + 32];
        int idxv = 0;
        if (lane < KK) idxv = g_idx[(size_t)p * KK + lane];
        int bbase = (p >> 12) << 12;

        float mx0 = -3.0e38f, mn0 = 3.0e38f, mx1 = -3.0e38f, mn1 = 3.0e38f;
#pragma unroll
        for (int k = 0; k < KK; k++) {
            int j = __shfl_sync(0xffffffffu, idxv, k);
            const float* uj = g_u + (size_t)(bbase + j) * OUTC;
            float z0 = uj[lane] + v0;
            float z1 = uj[lane + 32] + v1;
            mx0 = fmaxf(mx0, z0); mn0 = fminf(mn0, z0);
            mx1 = fmaxf(mx1, z1); mn1 = fminf(mn1, z1);
            lsum0 += z0; lsq0 = fmaf(z0, z0, lsq0);
            lsum1 += z1; lsq1 = fmaf(z1, z1, lsq1);
        }
        float* mxp = g_mx + (size_t)p * OUTC;
        float* mnp = g_mn + (size_t)p * OUTC;
        mxp[lane] = mx0; mxp[lane + 32] = mx1;
        mnp[lane] = mn0; mnp[lane + 32] = mn1;
    }

    atomicAdd(&ssum[lane], lsum0);
    atomicAdd(&ssum[lane + 32], lsum1);
    atomicAdd(&ssq[lane], lsq0);
    atomicAdd(&ssq[lane + 32], lsq1);
    __syncthreads();
    if (tid < OUTC) {
        atomicAdd(&g_sum[tid], ssum[tid]);
        atomicAdd(&g_sumsq[tid], ssq[tid]);
    }
}

// ===================== kernel E0: finalize BN affine =====================
__global__ void stats_kernel(const float* __restrict__ gamma, const float* __restrict__ beta) {
    int o = threadIdx.x;
    const float cnt = (float)((size_t)BB * NN * KK);
    float mean = g_sum[o] / cnt;
    float var = g_sumsq[o] / cnt - mean * mean;
    float s = gamma[o] * rsqrtf(var + 1e-5f);
    g_s[o] = s;
    g_t[o] = fmaf(-mean, s, beta[o]);
}

// ===================== kernel E: BN + LeakyReLU + transpose =====================
__global__ void __launch_bounds__(256) out_kernel(float* __restrict__ out) {
    __shared__ float tile[64][65];
    __shared__ float ss[OUTC], tt[OUTC];
    int tid = threadIdx.x;
    if (tid < OUTC) { ss[tid] = g_s[tid]; tt[tid] = g_t[tid]; }
    __syncthreads();

    int p0 = blockIdx.x * 64;
    int b = p0 >> 12;
    int n0 = p0 & (NN - 1);

#pragma unroll
    for (int j = 0; j < 16; j++) {
        int i = tid + j * 256;
        int nn = i >> 6, o = i & 63;
        size_t base = (size_t)(p0 + nn) * OUTC + o;
        float s = ss[o];
        float z = (s >= 0.f) ? g_mx[base] : g_mn[base];
        float y = fmaf(s, z, tt[o]);
        y = (y >= 0.f) ? y : 0.2f * y;
        tile[o][nn] = y;
    }
    __syncthreads();
#pragma unroll
    for (int j = 0; j < 16; j++) {
        int i = tid + j * 256;
        int o = i >> 6, nn = i & 63;
        out[((size_t)(b * OUTC + o)) * NN + n0 + nn] = tile[o][nn];
    }
}

// ===================== launch =====================
extern "C" void kernel_launch(void* const* d_in, const int* in_sizes, int n_in,
                              void* d_out, int out_size) {
    const float* x     = (const float*)d_in[0];
    const float* W     = (const float*)d_in[1];
    const float* gamma = (const float*)d_in[2];
    const float* beta  = (const float*)d_in[3];
    float* out = (float*)d_out;

    cudaFuncSetAttribute(knn_gemm_kernel, cudaFuncAttributeMaxDynamicSharedMemorySize, SM_TOTAL);

    prep_kernel<<<(BB * NN) / 128, 128>>>(x);
    knn_gemm_kernel<<<BB * (NN / TM), 256, SM_TOTAL>>>();
    select_rerank_kernel<<<BB * NN, 128>>>();
    gemm_uv_kernel<<<dim3(NN / 128, 8, BB), 128>>>(x, W);
    edge_kernel<<<(BB * NN) / 64, 256>>>();
    stats_kernel<<<1, OUTC>>>(gamma, beta);
    out_kernel<<<(BB * NN) / 64, 256>>>(out);
}

// round 9
// speedup vs baseline: 1.0378x; 1.0378x over previous
#include <cuda_runtime.h>
#include <cuda_fp16.h>
#include <cstdint>

#define BB 8
#define CC 64
#define NN 4096
#define KK 20
#define NCAND 48
#define NTARGET 24
#define OUTC 64
#define TM 128
#define TN 128

// ===================== device scratch (allocation-free) =====================
__device__ __half g_hi[(size_t)BB * NN * CC];
__device__ float g_xp[(size_t)BB * NN * CC];          // point-major fp32 copy
__device__ float g_sq[BB * NN];
__device__ unsigned short g_scor[(size_t)BB * NN * NN];  // flipped-fp16 scores, 256MB
__device__ int   g_idx[BB * NN * KK];
__device__ float g_u[(size_t)BB * NN * OUTC];
__device__ float g_v[(size_t)BB * NN * OUTC];
__device__ float g_mx[(size_t)BB * NN * OUTC];
__device__ float g_mn[(size_t)BB * NN * OUTC];
__device__ float g_sum[OUTC];
__device__ float g_sumsq[OUTC];
__device__ float g_s[OUTC];
__device__ float g_t[OUTC];

// ===================== helpers =====================
__device__ __forceinline__ void ldsm_x4(uint32_t addr, uint32_t* r) {
    asm volatile("ldmatrix.sync.aligned.m8n8.x4.shared.b16 {%0,%1,%2,%3}, [%4];"
                 : "=r"(r[0]), "=r"(r[1]), "=r"(r[2]), "=r"(r[3]) : "r"(addr));
}
__device__ __forceinline__ void mma16816(float* d, const uint32_t* a, const uint32_t* b) {
    asm volatile("mma.sync.aligned.m16n8k16.row.col.f32.f16.f16.f32 "
                 "{%0,%1,%2,%3}, {%4,%5,%6,%7}, {%8,%9}, {%0,%1,%2,%3};"
                 : "+f"(d[0]), "+f"(d[1]), "+f"(d[2]), "+f"(d[3])
                 : "r"(a[0]), "r"(a[1]), "r"(a[2]), "r"(a[3]), "r"(b[0]), "r"(b[1]));
}
__device__ __forceinline__ uint32_t smem_u32(const void* p) {
    uint32_t a;
    asm("{ .reg .u64 t; cvta.to.shared.u64 t, %1; cvt.u32.u64 %0, t; }" : "=r"(a) : "l"(p));
    return a;
}
// two floats -> two flipped-fp16 (monotone: smaller float => smaller u16), packed
__device__ __forceinline__ uint32_t fflip16x2(float a, float b) {
    __half2 h2 = __floats2half2_rn(a, b);
    uint32_t u = *reinterpret_cast<uint32_t*>(&h2);
    uint32_t xorv = 0x80008000u | (((u >> 15) & 0x00010001u) * 0x7FFFu);
    return u ^ xorv;
}

// ===================== kernel A: sq norms + fp16 hi + fp32 point-major =====================
__global__ void __launch_bounds__(128) prep_kernel(const float* __restrict__ x) {
    int p = blockIdx.x * 128 + threadIdx.x;
    int b = p >> 12;
    int n = p & (NN - 1);
    const float* xb = x + (size_t)b * CC * NN + n;
    float s = 0.f;
#pragma unroll
    for (int g = 0; g < 8; g++) {
        uint4 h4;
        unsigned short* hp = (unsigned short*)&h4;
        float vf[8];
#pragma unroll
        for (int e = 0; e < 8; e++) {
            float v = xb[(size_t)(g * 8 + e) * NN];
            vf[e] = v;
            s = fmaf(v, v, s);
            hp[e] = __half_as_ushort(__float2half_rn(v));
        }
        *reinterpret_cast<uint4*>(g_hi + (size_t)p * CC + g * 8) = h4;
        *reinterpret_cast<float4*>(g_xp + (size_t)p * CC + g * 8) =
            make_float4(vf[0], vf[1], vf[2], vf[3]);
        *reinterpret_cast<float4*>(g_xp + (size_t)p * CC + g * 8 + 4) =
            make_float4(vf[4], vf[5], vf[6], vf[7]);
    }
    g_sq[p] = s;
    if (blockIdx.x == 0 && threadIdx.x < OUTC) {
        g_sum[threadIdx.x] = 0.f;
        g_sumsq[threadIdx.x] = 0.f;
    }
}

// ===================== kernel B1: HMMA GEMM, SM-balanced unit schedule =====================
#define SM_A     0          /* 128*144 = 18432 */
#define SM_B     18432      /* 2*18432 = 36864 */
#define SM_SQS   55296      /* 2*128*4 = 1024 */
#define SM_TOTAL 56320

// flattened unit space: u in [0, 8192), rtg = u>>5 (b = rtg>>5, row-tile = rtg&31), ct = u&31
__global__ void __launch_bounds__(256, 2) knn_gemm_kernel() {
    extern __shared__ char sm[];
    const uint32_t smb = smem_u32(sm);
    const int tid = threadIdx.x;
    const int wid = tid >> 5;
    const int lane = tid & 31;

    // ---- static SM-balanced range: paired CTAs (bid,bid+148) get 28 units each,
    //      singly-resident CTAs (bids 108..147) get 54 ----
    int bid = blockIdx.x;
    int ustart, uend;
    if (bid < 108)      { ustart = bid * 28;                uend = ustart + 28; }
    else if (bid >= 148){ ustart = 3024 + (bid - 148) * 28; uend = ustart + 28; }
    else                { ustart = 6048 + (bid - 108) * 54; uend = ustart + 54;
                          if (uend > 8192) uend = 8192; }

    float* sqs = (float*)(sm + SM_SQS);

    // ---- initial A tile ----
    int rtg = ustart >> 5;
    const __half* hi_a = g_hi + (size_t)(rtg >> 5) * NN * CC;
    {
        int row0 = (rtg & 31) * TM;
        for (int t = 0; t < 4; t++) {
            int i = tid + t * 256;
            int m = i >> 3, j = i & 7;
            *reinterpret_cast<uint4*>(sm + SM_A + m * 144 + j * 16) =
                *reinterpret_cast<const uint4*>(hi_a + (size_t)(row0 + m) * CC + j * 8);
        }
    }
    // ---- initial B tile ----
    {
        int ct = ustart & 31;
        int b = rtg >> 5;
        const __half* hb = g_hi + (size_t)b * NN * CC;
        for (int t = 0; t < 4; t++) {
            int i = tid + t * 256;
            int n = i >> 3, j = i & 7;
            *reinterpret_cast<uint4*>(sm + SM_B + n * 144 + j * 16) =
                *reinterpret_cast<const uint4*>(hb + (size_t)(ct * TN + n) * CC + j * 8);
        }
        if (tid < 128) sqs[tid] = g_sq[b * NN + ct * TN + tid];
    }
    __syncthreads();

    const int m0 = wid * 16;
    const int g = lane >> 2, t4 = lane & 3;
    uint4 pre[4];
    float sqnext = 0.f;

    for (int u = ustart; u < uend; u++) {
        int buf = (u - ustart) & 1;
        uint32_t bsm = smb + SM_B + (uint32_t)buf * 18432u;
        const int rtg_u = u >> 5;
        const int b_u = rtg_u >> 5;
        const int row0_u = (rtg_u & 31) * TM;
        const int ct_u = u & 31;

        // prefetch next unit's B tile + sq into registers (overlaps MMA)
        if (u + 1 < uend) {
            int rtg2 = (u + 1) >> 5;
            int b2 = rtg2 >> 5;
            int ct2 = (u + 1) & 31;
            const __half* hb2 = g_hi + (size_t)b2 * NN * CC;
#pragma unroll
            for (int t = 0; t < 4; t++) {
                int i = tid + t * 256;
                int n = i >> 3, j = i & 7;
                pre[t] = *reinterpret_cast<const uint4*>(hb2 + (size_t)(ct2 * TN + n) * CC + j * 8);
            }
            if (tid < 128) sqnext = g_sq[b2 * NN + ct2 * TN + tid];
        }

        // ---- MMA: D[128x128] = A(128x64) . B^T(64x128) ----
        float acc[16][4];
#pragma unroll
        for (int nt = 0; nt < 16; nt++)
#pragma unroll
            for (int e = 0; e < 4; e++) acc[nt][e] = 0.f;

#pragma unroll
        for (int ks = 0; ks < 4; ks++) {
            uint32_t ah[4];
            uint32_t aoff = (uint32_t)(m0 + (lane & 15)) * 144u +
                            (uint32_t)(ks * 16 + ((lane >> 4) << 3)) * 2u;
            ldsm_x4(smb + SM_A + aoff, ah);
#pragma unroll
            for (int ntp = 0; ntp < 8; ntp++) {
                uint32_t bh[4];
                uint32_t bn = (uint32_t)(ntp * 16 + ((lane >> 4) << 3) + (lane & 7));
                uint32_t bk = (uint32_t)(ks * 16 + (((lane >> 3) & 1) << 3));
                ldsm_x4(bsm + bn * 144u + bk * 2u, bh);
                mma16816(acc[2 * ntp],     ah, bh);
                mma16816(acc[2 * ntp + 1], ah, bh + 2);
            }
        }

        __syncthreads();   // all warps done with A and B[buf] reads

        // store next B tile + sqs into buf^1
        if (u + 1 < uend) {
            char* dstb = sm + SM_B + (buf ^ 1) * 18432;
#pragma unroll
            for (int t = 0; t < 4; t++) {
                int i = tid + t * 256;
                int n = i >> 3, j = i & 7;
                *reinterpret_cast<uint4*>(dstb + n * 144 + j * 16) = pre[t];
            }
            if (tid < 128) sqs[(buf ^ 1) * 128 + tid] = sqnext;

            // A reload on row-tile crossing (rare: <=2 per CTA)
            int rtg2 = (u + 1) >> 5;
            if (rtg2 != rtg) {
                rtg = rtg2;
                hi_a = g_hi + (size_t)(rtg >> 5) * NN * CC;
                int row0n = (rtg & 31) * TM;
                for (int t = 0; t < 4; t++) {
                    int i = tid + t * 256;
                    int m = i >> 3, j = i & 7;
                    *reinterpret_cast<uint4*>(sm + SM_A + m * 144 + j * 16) =
                        *reinterpret_cast<const uint4*>(hi_a + (size_t)(row0n + m) * CC + j * 8);
                }
            }
        }

        // ---- epilogue: score + flip-to-u16 + direct streaming stores ----
        {
            const float* sqb = sqs + buf * 128;
            unsigned short* dout = g_scor + ((size_t)(b_u * NN) + row0_u + m0 + g) * NN + ct_u * TN;
#pragma unroll
            for (int nt = 0; nt < 16; nt++) {
                int c0 = nt * 8 + t4 * 2;
                float2 sq2 = *reinterpret_cast<const float2*>(sqb + c0);
                uint32_t o0 = fflip16x2(fmaf(-2.f, acc[nt][0], sq2.x),
                                        fmaf(-2.f, acc[nt][1], sq2.y));
                uint32_t o1 = fflip16x2(fmaf(-2.f, acc[nt][2], sq2.x),
                                        fmaf(-2.f, acc[nt][3], sq2.y));
                __stcs(reinterpret_cast<uint32_t*>(dout + c0), o0);
                __stcs(reinterpret_cast<uint32_t*>(dout + (size_t)8 * NN + c0), o1);
            }
        }
        __syncthreads();   // B[buf^1] + A reload complete before next MMA
    }
}

// ===================== kernel B2: fused select (binary search) + exact rerank =====================
__global__ void __launch_bounds__(128) select_rerank_kernel() {
    __shared__ uint32_t wsum[2][4];
    __shared__ uint32_t counter;
    __shared__ int   cidx[NCAND];
    __shared__ float csc[NCAND];

    const int tid = threadIdx.x;
    const int wrp = tid >> 5;
    const int lane = tid & 31;
    const int p = blockIdx.x;
    const uint4* r4 = reinterpret_cast<const uint4*>(g_scor + (size_t)p * NN);

    // load 32 u16 scores per thread (coalesced uint4, streaming)
    uint4 v[4];
#pragma unroll
    for (int j = 0; j < 4; j++) v[j] = __ldcs(r4 + j * 128 + tid);

    uint32_t lo = 0, hi = 0x10000u, cut = 0x10000u;

#pragma unroll 1
    for (int it = 0; it < 17; it++) {
        uint32_t mid = (lo + hi) >> 1;
        uint32_t c = 0;
#pragma unroll
        for (int j = 0; j < 4; j++) {
            const uint32_t* u4 = (const uint32_t*)&v[j];
#pragma unroll
            for (int e = 0; e < 4; e++) {
                uint32_t u = u4[e];
                c += ((u & 0xFFFFu) < mid) + ((u >> 16) < mid);
            }
        }
        c = __reduce_add_sync(0xffffffffu, c);
        if (lane == 0) wsum[it & 1][wrp] = c;
        __syncthreads();
        uint32_t tot = wsum[it & 1][0] + wsum[it & 1][1] + wsum[it & 1][2] + wsum[it & 1][3];
        if (tot >= NTARGET && tot <= NCAND) { cut = mid; break; }
        if (tot >= NTARGET) hi = mid; else lo = mid;
        if (hi - lo <= 1) { cut = hi; break; }
    }

    if (tid == 0) counter = 0;
    __syncthreads();

    // compaction into smem
#pragma unroll
    for (int j = 0; j < 4; j++) {
        const uint32_t* u4 = (const uint32_t*)&v[j];
#pragma unroll
        for (int e = 0; e < 4; e++) {
            uint32_t u = u4[e];
            int i32 = 4 * (j * 128 + tid) + e;
            if ((u & 0xFFFFu) < cut) {
                uint32_t slot = atomicAdd(&counter, 1);
                if (slot < NCAND) cidx[slot] = 2 * i32;
            }
            if ((u >> 16) < cut) {
                uint32_t slot = atomicAdd(&counter, 1);
                if (slot < NCAND) cidx[slot] = 2 * i32 + 1;
            }
        }
    }
    __syncthreads();
    int cnt = counter < NCAND ? (int)counter : NCAND;
    int bbase = (p >> 12) << 12;

    // exact fp32 rescoring: one thread per candidate
    if (tid < NCAND) {
        if (tid < cnt) {
            int c = cidx[tid];
            const float* xr = g_xp + (size_t)p * CC;
            const float* xc = g_xp + (size_t)(bbase + c) * CC;
            float d = 0.f;
#pragma unroll
            for (int i = 0; i < 16; i++) {
                float4 a = *reinterpret_cast<const float4*>(xr + i * 4);
                float4 bq = *reinterpret_cast<const float4*>(xc + i * 4);
                d = fmaf(a.x, bq.x, d);
                d = fmaf(a.y, bq.y, d);
                d = fmaf(a.z, bq.z, d);
                d = fmaf(a.w, bq.w, d);
            }
            csc[tid] = fmaf(-2.f, d, g_sq[bbase + c]);
        } else {
            csc[tid] = 3.0e38f;
            cidx[tid] = 0x7fffffff;
        }
    }
    __syncthreads();

    // rank counting -> top-20
    if (tid < NCAND) {
        float s = csc[tid];
        int   ii = cidx[tid];
        int r = 0;
#pragma unroll
        for (int j = 0; j < NCAND; j++) {
            float sj = csc[j];
            int ij = cidx[j];
            r += (sj < s) || (sj == s && ij < ii);
        }
        if (r < KK) g_idx[(size_t)p * KK + r] = ii;
    }
}

// ===================== kernel C: u = W1 @ x, v = (W2-W1) @ x (8 outputs/thread) =====================
__global__ void __launch_bounds__(128) gemm_uv_kernel(const float* __restrict__ x,
                                                      const float* __restrict__ W) {
    int b = blockIdx.z, og = blockIdx.y;
    int n = blockIdx.x * 128 + threadIdx.x;

    __shared__ float W1s[8][64];
    __shared__ float Wds[8][64];
    for (int i = threadIdx.x; i < 8 * 64; i += 128) {
        int oo = i >> 6, c = i & 63;
        int o = og * 8 + oo;
        float w1 = W[o * 2 * CC + c];
        float w2 = W[o * 2 * CC + CC + c];
        W1s[oo][c] = w1;
        Wds[oo][c] = w2 - w1;
    }
    __syncthreads();

    float ua[8], va[8];
#pragma unroll
    for (int oo = 0; oo < 8; oo++) { ua[oo] = 0.f; va[oo] = 0.f; }

    const float* xb = x + (size_t)b * CC * NN + n;
#pragma unroll
    for (int ch = 0; ch < CC; ch++) {
        float xv = xb[(size_t)ch * NN];
#pragma unroll
        for (int oo = 0; oo < 8; oo++) {
            ua[oo] = fmaf(W1s[oo][ch], xv, ua[oo]);
            va[oo] = fmaf(Wds[oo][ch], xv, va[oo]);
        }
    }

    float* up = g_u + ((size_t)b * NN + n) * OUTC + og * 8;
    float* vp = g_v + ((size_t)b * NN + n) * OUTC + og * 8;
#pragma unroll
    for (int oo = 0; oo < 8; oo += 4) {
        *reinterpret_cast<float4*>(up + oo) = make_float4(ua[oo], ua[oo + 1], ua[oo + 2], ua[oo + 3]);
        *reinterpret_cast<float4*>(vp + oo) = make_float4(va[oo], va[oo + 1], va[oo + 2], va[oo + 3]);
    }
}

// ===================== kernel D: edges =====================
__global__ void __launch_bounds__(256) edge_kernel() {
    __shared__ float ssum[OUTC];
    __shared__ float ssq[OUTC];
    int tid = threadIdx.x, lane = tid & 31, wrp = tid >> 5;
    if (tid < OUTC) { ssum[tid] = 0.f; ssq[tid] = 0.f; }
    __syncthreads();

    int p0 = blockIdx.x * 64;
    float lsum0 = 0.f, lsq0 = 0.f, lsum1 = 0.f, lsq1 = 0.f;

    for (int i = 0; i < 8; i++) {
        int p = p0 + wrp * 8 + i;
        const float* vp = g_v + (size_t)p * OUTC;
        float v0 = vp[lane], v1 = vp[lane + 32];
        int idxv = 0;
        if (lane < KK) idxv = g_idx[(size_t)p * KK + lane];
        int bbase = (p >> 12) << 12;

        float mx0 = -3.0e38f, mn0 = 3.0e38f, mx1 = -3.0e38f, mn1 = 3.0e38f;
#pragma unroll
        for (int k = 0; k < KK; k++) {
            int j = __shfl_sync(0xffffffffu, idxv, k);
            const float* uj = g_u + (size_t)(bbase + j) * OUTC;
            float z0 = uj[lane] + v0;
            float z1 = uj[lane + 32] + v1;
            mx0 = fmaxf(mx0, z0); mn0 = fminf(mn0, z0);
            mx1 = fmaxf(mx1, z1); mn1 = fminf(mn1, z1);
            lsum0 += z0; lsq0 = fmaf(z0, z0, lsq0);
            lsum1 += z1; lsq1 = fmaf(z1, z1, lsq1);
        }
        float* mxp = g_mx + (size_t)p * OUTC;
        float* mnp = g_mn + (size_t)p * OUTC;
        mxp[lane] = mx0; mxp[lane + 32] = mx1;
        mnp[lane] = mn0; mnp[lane + 32] = mn1;
    }

    atomicAdd(&ssum[lane], lsum0);
    atomicAdd(&ssum[lane + 32], lsum1);
    atomicAdd(&ssq[lane], lsq0);
    atomicAdd(&ssq[lane + 32], lsq1);
    __syncthreads();
    if (tid < OUTC) {
        atomicAdd(&g_sum[tid], ssum[tid]);
        atomicAdd(&g_sumsq[tid], ssq[tid]);
    }
}

// ===================== kernel E0: finalize BN affine =====================
__global__ void stats_kernel(const float* __restrict__ gamma, const float* __restrict__ beta) {
    int o = threadIdx.x;
    const float cnt = (float)((size_t)BB * NN * KK);
    float mean = g_sum[o] / cnt;
    float var = g_sumsq[o] / cnt - mean * mean;
    float s = gamma[o] * rsqrtf(var + 1e-5f);
    g_s[o] = s;
    g_t[o] = fmaf(-mean, s, beta[o]);
}

// ===================== kernel E: BN + LeakyReLU + transpose =====================
__global__ void __launch_bounds__(256) out_kernel(float* __restrict__ out) {
    __shared__ float tile[64][65];
    __shared__ float ss[OUTC], tt[OUTC];
    int tid = threadIdx.x;
    if (tid < OUTC) { ss[tid] = g_s[tid]; tt[tid] = g_t[tid]; }
    __syncthreads();

    int p0 = blockIdx.x * 64;
    int b = p0 >> 12;
    int n0 = p0 & (NN - 1);

#pragma unroll
    for (int j = 0; j < 16; j++) {
        int i = tid + j * 256;
        int nn = i >> 6, o = i & 63;
        size_t base = (size_t)(p0 + nn) * OUTC + o;
        float s = ss[o];
        float z = (s >= 0.f) ? g_mx[base] : g_mn[base];
        float y = fmaf(s, z, tt[o]);
        y = (y >= 0.f) ? y : 0.2f * y;
        tile[o][nn] = y;
    }
    __syncthreads();
#pragma unroll
    for (int j = 0; j < 16; j++) {
        int i = tid + j * 256;
        int o = i >> 6, nn = i & 63;
        out[((size_t)(b * OUTC + o)) * NN + n0 + nn] = tile[o][nn];
    }
}

// ===================== launch =====================
extern "C" void kernel_launch(void* const* d_in, const int* in_sizes, int n_in,
                              void* d_out, int out_size) {
    const float* x     = (const float*)d_in[0];
    const float* W     = (const float*)d_in[1];
    const float* gamma = (const float*)d_in[2];
    const float* beta  = (const float*)d_in[3];
    float* out = (float*)d_out;

    cudaFuncSetAttribute(knn_gemm_kernel, cudaFuncAttributeMaxDynamicSharedMemorySize, SM_TOTAL);

    prep_kernel<<<(BB * NN) / 128, 128>>>(x);
    knn_gemm_kernel<<<256, 256, SM_TOTAL>>>();
    select_rerank_kernel<<<BB * NN, 128>>>();
    gemm_uv_kernel<<<dim3(NN / 128, 8, BB), 128>>>(x, W);
    edge_kernel<<<(BB * NN) / 64, 256>>>();
    stats_kernel<<<1, OUTC>>>(gamma, beta);
    out_kernel<<<(BB * NN) / 64, 256>>>(out);
}

// round 10
// speedup vs baseline: 1.1197x; 1.0789x over previous
#include <cuda_runtime.h>
#include <cuda_fp16.h>
#include <cstdint>

#define BB 8
#define CC 64
#define NN 4096
#define KK 20
#define NCAND 48
#define NTARGET 24
#define OUTC 64
#define TM 128
#define TN 128

// ===================== device scratch (allocation-free) =====================
__device__ __half g_hi[(size_t)BB * NN * CC];
__device__ float g_xp[(size_t)BB * NN * CC];          // point-major fp32 copy
__device__ float g_sq[BB * NN];
__device__ unsigned short g_scor[(size_t)BB * NN * NN];  // flipped-fp16 scores, 256MB
__device__ int   g_idx[BB * NN * KK];
__device__ float g_u[(size_t)BB * NN * OUTC];
__device__ float g_v[(size_t)BB * NN * OUTC];
__device__ float g_mx[(size_t)BB * NN * OUTC];
__device__ float g_mn[(size_t)BB * NN * OUTC];
__device__ float g_sum[OUTC];
__device__ float g_sumsq[OUTC];
__device__ float g_s[OUTC];
__device__ float g_t[OUTC];

// ===================== helpers =====================
__device__ __forceinline__ void ldsm_x4(uint32_t addr, uint32_t* r) {
    asm volatile("ldmatrix.sync.aligned.m8n8.x4.shared.b16 {%0,%1,%2,%3}, [%4];"
                 : "=r"(r[0]), "=r"(r[1]), "=r"(r[2]), "=r"(r[3]) : "r"(addr));
}
// fp16-accumulate HMMA: D,C are 2 regs (half2 x2)
__device__ __forceinline__ void mma16816h(uint32_t* d, const uint32_t* a, const uint32_t* b) {
    asm volatile("mma.sync.aligned.m16n8k16.row.col.f16.f16.f16.f16 "
                 "{%0,%1}, {%2,%3,%4,%5}, {%6,%7}, {%0,%1};"
                 : "+r"(d[0]), "+r"(d[1])
                 : "r"(a[0]), "r"(a[1]), "r"(a[2]), "r"(a[3]), "r"(b[0]), "r"(b[1]));
}
__device__ __forceinline__ uint32_t smem_u32(const void* p) {
    uint32_t a;
    asm("{ .reg .u64 t; cvta.to.shared.u64 t, %1; cvt.u32.u64 %0, t; }" : "=r"(a) : "l"(p));
    return a;
}
// flip packed half2 to monotone u16 pair (smaller float => smaller u16)
__device__ __forceinline__ uint32_t flip16x2u(uint32_t u) {
    return u ^ (0x80008000u | (((u >> 15) & 0x00010001u) * 0x7FFFu));
}
// two floats -> flipped-fp16 pair (used by nothing hot; kept for clarity)
__device__ __forceinline__ uint32_t fflip16x2(float a, float b) {
    __half2 h2 = __floats2half2_rn(a, b);
    return flip16x2u(*reinterpret_cast<uint32_t*>(&h2));
}

// ===================== kernel A: sq norms + fp16 hi + fp32 point-major =====================
__global__ void __launch_bounds__(128) prep_kernel(const float* __restrict__ x) {
    int p = blockIdx.x * 128 + threadIdx.x;
    int b = p >> 12;
    int n = p & (NN - 1);
    const float* xb = x + (size_t)b * CC * NN + n;
    float s = 0.f;
#pragma unroll
    for (int g = 0; g < 8; g++) {
        uint4 h4;
        unsigned short* hp = (unsigned short*)&h4;
        float vf[8];
#pragma unroll
        for (int e = 0; e < 8; e++) {
            float v = xb[(size_t)(g * 8 + e) * NN];
            vf[e] = v;
            s = fmaf(v, v, s);
            hp[e] = __half_as_ushort(__float2half_rn(v));
        }
        *reinterpret_cast<uint4*>(g_hi + (size_t)p * CC + g * 8) = h4;
        *reinterpret_cast<float4*>(g_xp + (size_t)p * CC + g * 8) =
            make_float4(vf[0], vf[1], vf[2], vf[3]);
        *reinterpret_cast<float4*>(g_xp + (size_t)p * CC + g * 8 + 4) =
            make_float4(vf[4], vf[5], vf[6], vf[7]);
    }
    g_sq[p] = s;
    if (blockIdx.x == 0 && threadIdx.x < OUTC) {
        g_sum[threadIdx.x] = 0.f;
        g_sumsq[threadIdx.x] = 0.f;
    }
}

// ===================== kernel B1: HMMA(f16-acc) GEMM -> flipped-fp16 scores =====================
#define SM_A     0          /* 128*144 = 18432 */
#define SM_B     18432      /* 2*18432 = 36864 */
#define SM_SQS   55296      /* 2*64*4 = 512 (half2-packed sq) */
#define SM_TOTAL 55808

__global__ void __launch_bounds__(256, 2) knn_gemm_kernel() {
    extern __shared__ char sm[];
    const uint32_t smb = smem_u32(sm);
    const int tid = threadIdx.x;
    const int wid = tid >> 5;
    const int lane = tid & 31;
    const int b = blockIdx.y;
    const int row0 = blockIdx.x * TM;

    const __half* hi_b = g_hi + (size_t)b * NN * CC;
    uint32_t* sqs = (uint32_t*)(sm + SM_SQS);   // half2-packed per 2 cols

    // load A rows, padded stride 144B
    for (int t = 0; t < 4; t++) {
        int i = tid + t * 256;
        int m = i >> 3, j = i & 7;
        *reinterpret_cast<uint4*>(sm + SM_A + m * 144 + j * 16) =
            *reinterpret_cast<const uint4*>(hi_b + (size_t)(row0 + m) * CC + j * 8);
    }
    // B tile 0
    for (int t = 0; t < 4; t++) {
        int i = tid + t * 256;
        int n = i >> 3, j = i & 7;
        *reinterpret_cast<uint4*>(sm + SM_B + n * 144 + j * 16) =
            *reinterpret_cast<const uint4*>(hi_b + (size_t)n * CC + j * 8);
    }
    if (tid < 64) {
        float2 f = *reinterpret_cast<const float2*>(g_sq + b * NN + tid * 2);
        __half2 h = __floats2half2_rn(f.x, f.y);
        sqs[tid] = *reinterpret_cast<uint32_t*>(&h);
    }
    __syncthreads();

    const int m0 = wid * 16;
    const int g = lane >> 2, t4 = lane & 3;
    const __half2 neg2 = __float2half2_rn(-2.f);
    uint4 pre[4];
    float2 sqnext = make_float2(0.f, 0.f);

    for (int ct = 0; ct < NN / TN; ct++) {
        int buf = ct & 1;
        uint32_t bsm = smb + SM_B + (uint32_t)buf * 18432u;

        // prefetch next B tile + sq to registers (overlaps MMA)
        if (ct + 1 < NN / TN) {
            int col0 = (ct + 1) * TN;
#pragma unroll
            for (int t = 0; t < 4; t++) {
                int i = tid + t * 256;
                int n = i >> 3, j = i & 7;
                pre[t] = *reinterpret_cast<const uint4*>(hi_b + (size_t)(col0 + n) * CC + j * 8);
            }
            if (tid < 64) sqnext = *reinterpret_cast<const float2*>(g_sq + b * NN + col0 + tid * 2);
        }

        // ---- MMA: D[128x128] = A(128x64) . B^T(64x128), fp16 accumulate ----
        uint32_t acc[16][2];
#pragma unroll
        for (int nt = 0; nt < 16; nt++) { acc[nt][0] = 0u; acc[nt][1] = 0u; }

#pragma unroll
        for (int ks = 0; ks < 4; ks++) {
            uint32_t ah[4];
            uint32_t aoff = (uint32_t)(m0 + (lane & 15)) * 144u +
                            (uint32_t)(ks * 16 + ((lane >> 4) << 3)) * 2u;
            ldsm_x4(smb + SM_A + aoff, ah);
#pragma unroll
            for (int ntp = 0; ntp < 8; ntp++) {
                uint32_t bh[4];
                uint32_t bn = (uint32_t)(ntp * 16 + ((lane >> 4) << 3) + (lane & 7));
                uint32_t bk = (uint32_t)(ks * 16 + (((lane >> 3) & 1) << 3));
                ldsm_x4(bsm + bn * 144u + bk * 2u, bh);
                mma16816h(acc[2 * ntp],     ah, bh);
                mma16816h(acc[2 * ntp + 1], ah, bh + 2);
            }
        }

        __syncthreads();   // MMA reads of B[buf] + sqs[buf] done

        // store next B tile + sqs into buf^1
        if (ct + 1 < NN / TN) {
            char* dstb = sm + SM_B + (buf ^ 1) * 18432;
#pragma unroll
            for (int t = 0; t < 4; t++) {
                int i = tid + t * 256;
                int n = i >> 3, j = i & 7;
                *reinterpret_cast<uint4*>(dstb + n * 144 + j * 16) = pre[t];
            }
            if (tid < 64) {
                __half2 h = __floats2half2_rn(sqnext.x, sqnext.y);
                sqs[(buf ^ 1) * 64 + tid] = *reinterpret_cast<uint32_t*>(&h);
            }
        }

        // ---- epilogue: score = hfma2(inner, -2, sq) + flip + direct stores ----
        {
            const uint32_t* sqb = sqs + buf * 64;
            unsigned short* dout = g_scor + ((size_t)(b * NN) + row0 + m0 + g) * NN + ct * TN;
#pragma unroll
            for (int nt = 0; nt < 16; nt++) {
                int c0 = nt * 8 + t4 * 2;
                uint32_t squ = sqb[nt * 4 + t4];
                __half2 sqh = *reinterpret_cast<__half2*>(&squ);
                __half2 s0 = __hfma2(*reinterpret_cast<__half2*>(&acc[nt][0]), neg2, sqh);
                __half2 s1 = __hfma2(*reinterpret_cast<__half2*>(&acc[nt][1]), neg2, sqh);
                *reinterpret_cast<uint32_t*>(dout + c0) =
                    flip16x2u(*reinterpret_cast<uint32_t*>(&s0));
                *reinterpret_cast<uint32_t*>(dout + (size_t)8 * NN + c0) =
                    flip16x2u(*reinterpret_cast<uint32_t*>(&s1));
            }
        }
        __syncthreads();   // B[buf^1] fully written before next MMA
    }
}

// ===================== kernel B2: fused select (binary search) + exact rerank =====================
__global__ void __launch_bounds__(128) select_rerank_kernel() {
    __shared__ uint32_t wsum[2][4];
    __shared__ uint32_t counter;
    __shared__ int   cidx[NCAND];
    __shared__ float csc[NCAND];

    const int tid = threadIdx.x;
    const int wrp = tid >> 5;
    const int lane = tid & 31;
    const int p = blockIdx.x;
    const uint4* r4 = reinterpret_cast<const uint4*>(g_scor + (size_t)p * NN);

    // load 32 u16 scores per thread (coalesced uint4)
    uint4 v[4];
#pragma unroll
    for (int j = 0; j < 4; j++) v[j] = r4[j * 128 + tid];

    uint32_t lo = 0, hi = 0x10000u, cut = 0x10000u;

#pragma unroll 1
    for (int it = 0; it < 17; it++) {
        uint32_t mid = (lo + hi) >> 1;
        uint32_t c = 0;
#pragma unroll
        for (int j = 0; j < 4; j++) {
            const uint32_t* u4 = (const uint32_t*)&v[j];
#pragma unroll
            for (int e = 0; e < 4; e++) {
                uint32_t u = u4[e];
                c += ((u & 0xFFFFu) < mid) + ((u >> 16) < mid);
            }
        }
        c = __reduce_add_sync(0xffffffffu, c);
        if (lane == 0) wsum[it & 1][wrp] = c;
        __syncthreads();
        uint32_t tot = wsum[it & 1][0] + wsum[it & 1][1] + wsum[it & 1][2] + wsum[it & 1][3];
        if (tot >= NTARGET && tot <= NCAND) { cut = mid; break; }
        if (tot >= NTARGET) hi = mid; else lo = mid;
        if (hi - lo <= 1) { cut = hi; break; }
    }

    if (tid == 0) counter = 0;
    __syncthreads();

    // compaction into smem
#pragma unroll
    for (int j = 0; j < 4; j++) {
        const uint32_t* u4 = (const uint32_t*)&v[j];
#pragma unroll
        for (int e = 0; e < 4; e++) {
            uint32_t u = u4[e];
            int i32 = 4 * (j * 128 + tid) + e;
            if ((u & 0xFFFFu) < cut) {
                uint32_t slot = atomicAdd(&counter, 1);
                if (slot < NCAND) cidx[slot] = 2 * i32;
            }
            if ((u >> 16) < cut) {
                uint32_t slot = atomicAdd(&counter, 1);
                if (slot < NCAND) cidx[slot] = 2 * i32 + 1;
            }
        }
    }
    __syncthreads();
    int cnt = counter < NCAND ? (int)counter : NCAND;
    int bbase = (p >> 12) << 12;

    // exact fp32 rescoring: one thread per candidate
    if (tid < NCAND) {
        if (tid < cnt) {
            int c = cidx[tid];
            const float* xr = g_xp + (size_t)p * CC;
            const float* xc = g_xp + (size_t)(bbase + c) * CC;
            float d = 0.f;
#pragma unroll
            for (int i = 0; i < 16; i++) {
                float4 a = *reinterpret_cast<const float4*>(xr + i * 4);
                float4 bq = *reinterpret_cast<const float4*>(xc + i * 4);
                d = fmaf(a.x, bq.x, d);
                d = fmaf(a.y, bq.y, d);
                d = fmaf(a.z, bq.z, d);
                d = fmaf(a.w, bq.w, d);
            }
            csc[tid] = fmaf(-2.f, d, g_sq[bbase + c]);
        } else {
            csc[tid] = 3.0e38f;
            cidx[tid] = 0x7fffffff;
        }
    }
    __syncthreads();

    // rank counting -> top-20
    if (tid < NCAND) {
        float s = csc[tid];
        int   ii = cidx[tid];
        int r = 0;
#pragma unroll
        for (int j = 0; j < NCAND; j++) {
            float sj = csc[j];
            int ij = cidx[j];
            r += (sj < s) || (sj == s && ij < ii);
        }
        if (r < KK) g_idx[(size_t)p * KK + r] = ii;
    }
}

// ===================== kernel C: u = W1 @ x, v = (W2-W1) @ x (8 outputs/thread) =====================
__global__ void __launch_bounds__(128) gemm_uv_kernel(const float* __restrict__ x,
                                                      const float* __restrict__ W) {
    int b = blockIdx.z, og = blockIdx.y;
    int n = blockIdx.x * 128 + threadIdx.x;

    __shared__ float W1s[8][64];
    __shared__ float Wds[8][64];
    for (int i = threadIdx.x; i < 8 * 64; i += 128) {
        int oo = i >> 6, c = i & 63;
        int o = og * 8 + oo;
        float w1 = W[o * 2 * CC + c];
        float w2 = W[o * 2 * CC + CC + c];
        W1s[oo][c] = w1;
        Wds[oo][c] = w2 - w1;
    }
    __syncthreads();

    float ua[8], va[8];
#pragma unroll
    for (int oo = 0; oo < 8; oo++) { ua[oo] = 0.f; va[oo] = 0.f; }

    const float* xb = x + (size_t)b * CC * NN + n;
#pragma unroll
    for (int ch = 0; ch < CC; ch++) {
        float xv = xb[(size_t)ch * NN];
#pragma unroll
        for (int oo = 0; oo < 8; oo++) {
            ua[oo] = fmaf(W1s[oo][ch], xv, ua[oo]);
            va[oo] = fmaf(Wds[oo][ch], xv, va[oo]);
        }
    }

    float* up = g_u + ((size_t)b * NN + n) * OUTC + og * 8;
    float* vp = g_v + ((size_t)b * NN + n) * OUTC + og * 8;
#pragma unroll
    for (int oo = 0; oo < 8; oo += 4) {
        *reinterpret_cast<float4*>(up + oo) = make_float4(ua[oo], ua[oo + 1], ua[oo + 2], ua[oo + 3]);
        *reinterpret_cast<float4*>(vp + oo) = make_float4(va[oo], va[oo + 1], va[oo + 2], va[oo + 3]);
    }
}

// ===================== kernel D: edges =====================
__global__ void __launch_bounds__(256) edge_kernel() {
    __shared__ float ssum[OUTC];
    __shared__ float ssq[OUTC];
    int tid = threadIdx.x, lane = tid & 31, wrp = tid >> 5;
    if (tid < OUTC) { ssum[tid] = 0.f; ssq[tid] = 0.f; }
    __syncthreads();

    int p0 = blockIdx.x * 64;
    float lsum0 = 0.f, lsq0 = 0.f, lsum1 = 0.f, lsq1 = 0.f;

    for (int i = 0; i < 8; i++) {
        int p = p0 + wrp * 8 + i;
        const float* vp = g_v + (size_t)p * OUTC;
        float v0 = vp[lane], v1 = vp[lane + 32];
        int idxv = 0;
        if (lane < KK) idxv = g_idx[(size_t)p * KK + lane];
        int bbase = (p >> 12) << 12;

        float mx0 = -3.0e38f, mn0 = 3.0e38f, mx1 = -3.0e38f, mn1 = 3.0e38f;
#pragma unroll
        for (int k = 0; k < KK; k++) {
            int j = __shfl_sync(0xffffffffu, idxv, k);
            const float* uj = g_u + (size_t)(bbase + j) * OUTC;
            float z0 = uj[lane] + v0;
            float z1 = uj[lane + 32] + v1;
            mx0 = fmaxf(mx0, z0); mn0 = fminf(mn0, z0);
            mx1 = fmaxf(mx1, z1); mn1 = fminf(mn1, z1);
            lsum0 += z0; lsq0 = fmaf(z0, z0, lsq0);
            lsum1 += z1; lsq1 = fmaf(z1, z1, lsq1);
        }
        float* mxp = g_mx + (size_t)p * OUTC;
        float* mnp = g_mn + (size_t)p * OUTC;
        mxp[lane] = mx0; mxp[lane + 32] = mx1;
        mnp[lane] = mn0; mnp[lane + 32] = mn1;
    }

    atomicAdd(&ssum[lane], lsum0);
    atomicAdd(&ssum[lane + 32], lsum1);
    atomicAdd(&ssq[lane], lsq0);
    atomicAdd(&ssq[lane + 32], lsq1);
    __syncthreads();
    if (tid < OUTC) {
        atomicAdd(&g_sum[tid], ssum[tid]);
        atomicAdd(&g_sumsq[tid], ssq[tid]);
    }
}

// ===================== kernel E0: finalize BN affine =====================
__global__ void stats_kernel(const float* __restrict__ gamma, const float* __restrict__ beta) {
    int o = threadIdx.x;
    const float cnt = (float)((size_t)BB * NN * KK);
    float mean = g_sum[o] / cnt;
    float var = g_sumsq[o] / cnt - mean * mean;
    float s = gamma[o] * rsqrtf(var + 1e-5f);
    g_s[o] = s;
    g_t[o] = fmaf(-mean, s, beta[o]);
}

// ===================== kernel E: BN + LeakyReLU + transpose =====================
__global__ void __launch_bounds__(256) out_kernel(float* __restrict__ out) {
    __shared__ float tile[64][65];
    __shared__ float ss[OUTC], tt[OUTC];
    int tid = threadIdx.x;
    if (tid < OUTC) { ss[tid] = g_s[tid]; tt[tid] = g_t[tid]; }
    __syncthreads();

    int p0 = blockIdx.x * 64;
    int b = p0 >> 12;
    int n0 = p0 & (NN - 1);

#pragma unroll
    for (int j = 0; j < 16; j++) {
        int i = tid + j * 256;
        int nn = i >> 6, o = i & 63;
        size_t base = (size_t)(p0 + nn) * OUTC + o;
        float s = ss[o];
        float z = (s >= 0.f) ? g_mx[base] : g_mn[base];
        float y = fmaf(s, z, tt[o]);
        y = (y >= 0.f) ? y : 0.2f * y;
        tile[o][nn] = y;
    }
    __syncthreads();
#pragma unroll
    for (int j = 0; j < 16; j++) {
        int i = tid + j * 256;
        int o = i >> 6, nn = i & 63;
        out[((size_t)(b * OUTC + o)) * NN + n0 + nn] = tile[o][nn];
    }
}

// ===================== launch =====================
extern "C" void kernel_launch(void* const* d_in, const int* in_sizes, int n_in,
                              void* d_out, int out_size) {
    const float* x     = (const float*)d_in[0];
    const float* W     = (const float*)d_in[1];
    const float* gamma = (const float*)d_in[2];
    const float* beta  = (const float*)d_in[3];
    float* out = (float*)d_out;

    cudaFuncSetAttribute(knn_gemm_kernel, cudaFuncAttributeMaxDynamicSharedMemorySize, SM_TOTAL);

    prep_kernel<<<(BB * NN) / 128, 128>>>(x);
    knn_gemm_kernel<<<dim3(NN / TM, BB), 256, SM_TOTAL>>>();
    select_rerank_kernel<<<BB * NN, 128>>>();
    gemm_uv_kernel<<<dim3(NN / 128, 8, BB), 128>>>(x, W);
    edge_kernel<<<(BB * NN) / 64, 256>>>();
    stats_kernel<<<1, OUTC>>>(gamma, beta);
    out_kernel<<<(BB * NN) / 64, 256>>>(out);
}